// round 1
// baseline (speedup 1.0000x reference)
#include <cuda_runtime.h>
#include <cuda_bf16.h>
#include <math.h>

// Problem sizes (fixed)
#define BATCH 64
#define SEQ   512
#define INDIM 512
#define HID   1024
#define OUTDIM 512

// Recurrence partitioning
#define RGROUPS 4          // batch groups
#define RBPG    16         // batches per group
#define RSLICES 32         // CTAs per group (H slices)
#define RHS     32         // H rows per CTA

// ---------------------------------------------------------------------------
// Scratch (static device arrays; no allocation allowed)
// ---------------------------------------------------------------------------
__device__ float g_xu[BATCH * SEQ * HID];     // 128 MB
__device__ float g_s[2][BATCH * HID];         // double-buffered state
__device__ unsigned g_cnt[RGROUPS];
__device__ unsigned g_phase[RGROUPS];

// ---------------------------------------------------------------------------
// Packed fp32x2 FMA (Blackwell FFMA2; only reachable via PTX fma.rn.f32x2)
// ---------------------------------------------------------------------------
union F2U { float2 f; unsigned long long u; };
__device__ __forceinline__ float2 ffma2(float2 a, float2 b, float2 c) {
    F2U A, B, C, D;
    A.f = a; B.f = b; C.f = c;
    asm("fma.rn.f32x2 %0, %1, %2, %3;" : "=l"(D.u) : "l"(A.u), "l"(B.u), "l"(C.u));
    return D.f;
}

__device__ __forceinline__ float accurate_tanh(float y) {
    // tanh via expf: ~1-2 ulp even under fast-math; avoids tanh.approx error
    float ay = fabsf(y);
    float e = __expf(-2.0f * ay);
    float r = (1.0f - e) / (1.0f + e);
    return copysignf(r, y);
}

// ---------------------------------------------------------------------------
// Generic C = A * B^T + bias ; A[M][K], B[N][K], C[M][N] (all row-major,
// K-contiguous).  Tile 32m x 32n, BK=64, 256 threads, 2x2 microtile,
// k-pair-packed f32x2 accumulation.  N = gridDim.x*32 (C stride).
// ---------------------------------------------------------------------------
__global__ __launch_bounds__(256) void gemm_nt_f32x2(
    const float* __restrict__ A, const float* __restrict__ B,
    const float* __restrict__ bias, float* __restrict__ C, int K)
{
    __shared__ __align__(16) float2 As[32 * 34];   // [k2][m], row stride 34
    __shared__ __align__(16) float2 Bs[32 * 34];   // [k2][n]

    const int tid = threadIdx.x;
    const int m0 = blockIdx.y * 32, n0 = blockIdx.x * 32;
    const int mp = tid >> 4, np = tid & 15;

    // load-slot decomposition: 512 float4 slots per tile, 2 per thread
    const int s1 = tid, s2 = tid + 256;
    const int lm1 = s1 >> 4, lk1 = s1 & 15;
    const int lm2 = s2 >> 4, lk2 = s2 & 15;

    float2 a00 = {0.f, 0.f}, a01 = {0.f, 0.f}, a10 = {0.f, 0.f}, a11 = {0.f, 0.f};

    for (int kc = 0; kc < K; kc += 64) {
        float4 va1 = *(const float4*)&A[(m0 + lm1) * K + kc + 4 * lk1];
        float4 va2 = *(const float4*)&A[(m0 + lm2) * K + kc + 4 * lk2];
        float4 vb1 = *(const float4*)&B[(n0 + lm1) * K + kc + 4 * lk1];
        float4 vb2 = *(const float4*)&B[(n0 + lm2) * K + kc + 4 * lk2];
        __syncthreads();   // protect previous iteration's reads
        As[(2 * lk1) * 34 + lm1]     = make_float2(va1.x, va1.y);
        As[(2 * lk1 + 1) * 34 + lm1] = make_float2(va1.z, va1.w);
        As[(2 * lk2) * 34 + lm2]     = make_float2(va2.x, va2.y);
        As[(2 * lk2 + 1) * 34 + lm2] = make_float2(va2.z, va2.w);
        Bs[(2 * lk1) * 34 + lm1]     = make_float2(vb1.x, vb1.y);
        Bs[(2 * lk1 + 1) * 34 + lm1] = make_float2(vb1.z, vb1.w);
        Bs[(2 * lk2) * 34 + lm2]     = make_float2(vb2.x, vb2.y);
        Bs[(2 * lk2 + 1) * 34 + lm2] = make_float2(vb2.z, vb2.w);
        __syncthreads();
        #pragma unroll
        for (int k2 = 0; k2 < 32; ++k2) {
            float4 xa = *(const float4*)&As[k2 * 34 + 2 * mp];
            float4 wb = *(const float4*)&Bs[k2 * 34 + 2 * np];
            float2 xl = {xa.x, xa.y}, xh = {xa.z, xa.w};
            float2 wl = {wb.x, wb.y}, wh = {wb.z, wb.w};
            a00 = ffma2(xl, wl, a00);
            a01 = ffma2(xl, wh, a01);
            a10 = ffma2(xh, wl, a10);
            a11 = ffma2(xh, wh, a11);
        }
    }

    const int N = gridDim.x * 32;
    const int m = m0 + 2 * mp, n = n0 + 2 * np;
    const float b0v = bias[n], b1v = bias[n + 1];
    C[m * N + n]           = a00.x + a00.y + b0v;
    C[m * N + n + 1]       = a01.x + a01.y + b1v;
    C[(m + 1) * N + n]     = a10.x + a10.y + b0v;
    C[(m + 1) * N + n + 1] = a11.x + a11.y + b1v;
}

// ---------------------------------------------------------------------------
// Init: zero state + barrier vars (re-run every replay for determinism)
// ---------------------------------------------------------------------------
__global__ void init_kernel()
{
    int i = blockIdx.x * blockDim.x + threadIdx.x;
    int nth = gridDim.x * blockDim.x;
    float* p = &g_s[0][0];
    for (int j = i; j < 2 * BATCH * HID; j += nth) p[j] = 0.0f;
    if (i < RGROUPS) { g_cnt[i] = 0; g_phase[i] = 0; }
}

// ---------------------------------------------------------------------------
// Persistent recurrence kernel.
// grid = 128 CTAs = 4 batch-groups x 32 H-slices, block = 256.
// Each CTA: Ww slice [32 x 1024] resident in SMEM (k-pair packed, padded),
// per step stages s[16 x 1024] into SMEM, computes y = s*Wwslice^T with
// f32x2 (2b x 2h microtile, K split across two 128-thread halves),
// tanh-finalizes, then group barrier (32 CTAs) via L2 atomics.
// ---------------------------------------------------------------------------
#define WWS_F2   (512 * 34)                        // float2 count
#define SS_OFF   (WWS_F2 * 8)                      // bytes
#define YP_OFF   (SS_OFF + RBPG * HID * 4)         // bytes
#define RNN_SMEM (YP_OFF + 2 * 512 * 4)            // 208896 B

__global__ __launch_bounds__(256, 1) void rnn_step_kernel(
    const float* __restrict__ Ww, const float* __restrict__ bw)
{
    extern __shared__ __align__(16) char smem[];
    float2* Wws = (float2*)smem;                 // [k2][h], row stride 34
    float*  Ss  = (float*)(smem + SS_OFF);       // [16][1024]
    float*  Yp  = (float*)(smem + YP_OFF);       // [2][512]

    const int tid   = threadIdx.x;
    const int g     = blockIdx.x >> 5;
    const int slice = blockIdx.x & 31;
    const int h0    = slice * RHS;
    const int b0    = g * RBPG;

    // Load Ww slice once: (k-pair, h) packed, padded stride 34 float2
    for (int i = tid; i < RHS * 256; i += 256) {   // 8192 float4 slots
        int h = i >> 8, k4 = i & 255;
        float4 v = *(const float4*)&Ww[(h0 + h) * HID + 4 * k4];
        Wws[(2 * k4) * 34 + h]     = make_float2(v.x, v.y);
        Wws[(2 * k4 + 1) * 34 + h] = make_float2(v.z, v.w);
    }

    const int half = tid >> 7, t2 = tid & 127;
    const int bp = t2 >> 4, hp = t2 & 15;
    const float2* wbase = Wws + (half * 256) * 34 + 2 * hp;   // float4 view base
    const float2* Ss2   = (const float2*)Ss;
    const float2* s0b   = Ss2 + (2 * bp) * 512 + half * 256;
    const float2* s1b   = s0b + 512;

    // finalize mapping: 512 outputs (b_local*32 + h), 2 per thread
    const int o1 = tid, o2 = tid + 256;
    const int bl1 = o1 >> 5, hh1 = o1 & 31;
    const int bl2 = o2 >> 5, hh2 = o2 & 31;
    const float bw1 = bw[h0 + hh1];
    const float bw2 = bw[h0 + hh2];
    const float* xup1 = &g_xu[((b0 + bl1) * SEQ) * HID + h0 + hh1];
    const float* xup2 = &g_xu[((b0 + bl2) * SEQ) * HID + h0 + hh2];

    for (int t = 0; t < SEQ; ++t) {
        const int cur = t & 1, nxt = cur ^ 1;
        // prefetch xu for this step (hides DRAM/L2 latency behind compute)
        const float xv1 = __ldg(xup1 + t * HID);
        const float xv2 = __ldg(xup2 + t * HID);

        // stage s for this group's 16 batches: 64 KB, coalesced float4 copy
        {
            const float4* src = (const float4*)&g_s[cur][b0 * HID];
            float4* dst = (float4*)Ss;
            #pragma unroll
            for (int i = 0; i < 16; ++i) dst[tid + i * 256] = src[tid + i * 256];
        }
        __syncthreads();

        // compute: 2b x 2h per thread over this half's 256 k-pairs
        float2 a00 = {0.f, 0.f}, a01 = {0.f, 0.f}, a10 = {0.f, 0.f}, a11 = {0.f, 0.f};
        #pragma unroll 8
        for (int k2 = 0; k2 < 256; ++k2) {
            float4 w  = *(const float4*)&wbase[k2 * 34];
            float2 sa = s0b[k2];
            float2 sb = s1b[k2];
            float2 wl = {w.x, w.y}, wh = {w.z, w.w};
            a00 = ffma2(sa, wl, a00);
            a01 = ffma2(sa, wh, a01);
            a10 = ffma2(sb, wl, a10);
            a11 = ffma2(sb, wh, a11);
        }
        {
            float* yph = Yp + half * 512;
            yph[(2 * bp) * 32 + 2 * hp]         = a00.x + a00.y;
            yph[(2 * bp) * 32 + 2 * hp + 1]     = a01.x + a01.y;
            yph[(2 * bp + 1) * 32 + 2 * hp]     = a10.x + a10.y;
            yph[(2 * bp + 1) * 32 + 2 * hp + 1] = a11.x + a11.y;
        }
        __syncthreads();

        // finalize: combine halves + xu + bias, tanh, write next state
        float y1 = Yp[o1] + Yp[512 + o1] + xv1 + bw1;
        float y2 = Yp[o2] + Yp[512 + o2] + xv2 + bw2;
        g_s[nxt][(b0 + bl1) * HID + h0 + hh1] = accurate_tanh(y1);
        g_s[nxt][(b0 + bl2) * HID + h0 + hh2] = accurate_tanh(y2);

        // group barrier (32 CTAs of this batch-group)
        if (t < SEQ - 1) {
            __threadfence();
            __syncthreads();
            if (tid == 0) {
                unsigned a = atomicAdd(&g_cnt[g], 1);
                if (a == RSLICES - 1) {
                    atomicExch(&g_cnt[g], 0);
                    __threadfence();
                    atomicExch(&g_phase[g], (unsigned)(t + 1));
                } else {
                    while (*(volatile unsigned*)&g_phase[g] < (unsigned)(t + 1)) { }
                }
                __threadfence();
            }
            __syncthreads();
        }
    }
}

// ---------------------------------------------------------------------------
// kernel_launch
// ---------------------------------------------------------------------------
extern "C" void kernel_launch(void* const* d_in, const int* in_sizes, int n_in,
                              void* d_out, int out_size)
{
    const float* x  = (const float*)d_in[0];
    const float* Wu = (const float*)d_in[1];
    const float* bu = (const float*)d_in[2];
    const float* Ww = (const float*)d_in[3];
    const float* bw = (const float*)d_in[4];
    const float* Wv = (const float*)d_in[5];
    const float* bv = (const float*)d_in[6];
    float* out = (float*)d_out;
    (void)in_sizes; (void)n_in; (void)out_size;

    cudaFuncSetAttribute(rnn_step_kernel,
                         cudaFuncAttributeMaxDynamicSharedMemorySize, RNN_SMEM);

    void* xu_ptr = nullptr;
    void* s_ptr  = nullptr;
    cudaGetSymbolAddress(&xu_ptr, g_xu);
    cudaGetSymbolAddress(&s_ptr, g_s);   // buffer 0 == final state (SEQ even)

    // 0) reset state + barriers (every replay)
    init_kernel<<<64, 256>>>();

    // 1) xu = x @ Wu^T + bu   (M=32768, N=1024, K=512)
    gemm_nt_f32x2<<<dim3(HID / 32, (BATCH * SEQ) / 32), 256>>>(
        x, Wu, bu, (float*)xu_ptr, INDIM);

    // 2) recurrence (persistent, 128 co-resident CTAs)
    rnn_step_kernel<<<RGROUPS * RSLICES, 256, RNN_SMEM>>>(Ww, bw);

    // 3) out = s_final @ Wv^T + bv   (M=64, N=512, K=1024)
    gemm_nt_f32x2<<<dim3(OUTDIM / 32, BATCH / 32), 256>>>(
        (const float*)s_ptr, Wv, bv, out, HID);
}

// round 3
// speedup vs baseline: 1.3493x; 1.3493x over previous
#include <cuda_runtime.h>
#include <math.h>

// Problem sizes (fixed)
#define BATCH  64
#define SEQ    512
#define INDIM  512
#define HID    1024
#define OUTDIM 512

// RNN partitioning: 4 batch-groups x 32 h-slices = 128 persistent CTAs
#define RGROUPS 4
#define RBPG    16
#define RSLICES 32
#define RHS     32

// ---------------------------------------------------------------------------
// Scratch (static device arrays; no allocation allowed)
// ---------------------------------------------------------------------------
__device__ float g_xu[BATCH * SEQ * HID];     // 128 MB
__device__ float g_s[2][BATCH * HID];         // double-buffered state
__device__ unsigned g_cnt[RGROUPS];
__device__ unsigned g_phase[RGROUPS];

// ---------------------------------------------------------------------------
// Packed fp32x2 FMA (Blackwell FFMA2; only reachable via PTX fma.rn.f32x2)
// ---------------------------------------------------------------------------
union F2U { float2 f; unsigned long long u; };
__device__ __forceinline__ float2 ffma2(float2 a, float2 b, float2 c) {
    F2U A, B, C, D;
    A.f = a; B.f = b; C.f = c;
    asm("fma.rn.f32x2 %0, %1, %2, %3;" : "=l"(D.u) : "l"(A.u), "l"(B.u), "l"(C.u));
    return D.f;
}

__device__ __forceinline__ float accurate_tanh(float y) {
    float ay = fabsf(y);
    float e = __expf(-2.0f * ay);
    float r = (1.0f - e) / (1.0f + e);
    return copysignf(r, y);
}

// ---------------------------------------------------------------------------
// Big GEMM: C = A * B^T + bias.  A[M][K], B[N][K] row-major (K contiguous).
// BM=64, BN=128, BK=16, 256 threads, thread tile 4m x 8n (f32x2 k-pair acc).
// Bs uses a split-position layout so each warp's compute load of B is 16
// contiguous 16B lines (2 wavefronts after broadcast dedup).
// ---------------------------------------------------------------------------
__device__ __forceinline__ int posB(int n) {
    // n in [0,128): np = n>>3 (owning thread col), e = n&7 (element)
    // pos = (e>>1)*32 + np*2 + (e&1)
    return (((n & 7) >> 1) << 5) + (((n >> 3)) << 1) + (n & 1);
}

__global__ __launch_bounds__(256) void gemm_nt_big(
    const float* __restrict__ A, const float* __restrict__ B,
    const float* __restrict__ bias, float* __restrict__ C, int K, int N)
{
    __shared__ __align__(16) float2 As[8 * 66];    // [k2][m], stride 66
    __shared__ __align__(16) float2 Bs[8 * 130];   // [k2][pos], stride 130

    const int tid = threadIdx.x;
    const int m0 = blockIdx.y * 64, n0 = blockIdx.x * 128;
    const int mp = tid >> 4, np = tid & 15;

    // staging coords
    const int lmA = tid >> 2, lkA = tid & 3;             // A: 256 float4 slots
    const int lnB0 = tid >> 2, lkB0 = tid & 3;           // B rows 0..63
    const int lnB1 = 64 + (tid >> 2), lkB1 = tid & 3;    // B rows 64..127
    const int pB0 = posB(lnB0), pB1 = posB(lnB1);

    float2 acc[4][8];
    #pragma unroll
    for (int i = 0; i < 4; ++i)
        #pragma unroll
        for (int j = 0; j < 8; ++j) acc[i][j] = make_float2(0.f, 0.f);

    for (int kc = 0; kc < K; kc += 16) {
        float4 va  = *(const float4*)&A[(m0 + lmA) * K + kc + 4 * lkA];
        float4 vb0 = *(const float4*)&B[(n0 + lnB0) * K + kc + 4 * lkB0];
        float4 vb1 = *(const float4*)&B[(n0 + lnB1) * K + kc + 4 * lkB1];
        __syncthreads();   // protect previous iteration's reads
        As[(2 * lkA) * 66 + lmA]       = make_float2(va.x, va.y);
        As[(2 * lkA + 1) * 66 + lmA]   = make_float2(va.z, va.w);
        Bs[(2 * lkB0) * 130 + pB0]     = make_float2(vb0.x, vb0.y);
        Bs[(2 * lkB0 + 1) * 130 + pB0] = make_float2(vb0.z, vb0.w);
        Bs[(2 * lkB1) * 130 + pB1]     = make_float2(vb1.x, vb1.y);
        Bs[(2 * lkB1 + 1) * 130 + pB1] = make_float2(vb1.z, vb1.w);
        __syncthreads();
        #pragma unroll
        for (int k2 = 0; k2 < 8; ++k2) {
            float4 a4a = *(const float4*)&As[k2 * 66 + mp * 4];
            float4 a4b = *(const float4*)&As[k2 * 66 + mp * 4 + 2];
            float2 sv[4] = { {a4a.x, a4a.y}, {a4a.z, a4a.w},
                             {a4b.x, a4b.y}, {a4b.z, a4b.w} };
            float2 wv[8];
            #pragma unroll
            for (int j = 0; j < 4; ++j) {
                float4 b4 = *(const float4*)&Bs[k2 * 130 + j * 32 + np * 2];
                wv[2 * j]     = make_float2(b4.x, b4.y);
                wv[2 * j + 1] = make_float2(b4.z, b4.w);
            }
            #pragma unroll
            for (int mi = 0; mi < 4; ++mi)
                #pragma unroll
                for (int ni = 0; ni < 8; ++ni)
                    acc[mi][ni] = ffma2(sv[mi], wv[ni], acc[mi][ni]);
        }
    }

    const int nb = n0 + np * 8;
    float4 bv0 = *(const float4*)&bias[nb];
    float4 bv1 = *(const float4*)&bias[nb + 4];
    #pragma unroll
    for (int mi = 0; mi < 4; ++mi) {
        float4 o0, o1;
        o0.x = acc[mi][0].x + acc[mi][0].y + bv0.x;
        o0.y = acc[mi][1].x + acc[mi][1].y + bv0.y;
        o0.z = acc[mi][2].x + acc[mi][2].y + bv0.z;
        o0.w = acc[mi][3].x + acc[mi][3].y + bv0.w;
        o1.x = acc[mi][4].x + acc[mi][4].y + bv1.x;
        o1.y = acc[mi][5].x + acc[mi][5].y + bv1.y;
        o1.z = acc[mi][6].x + acc[mi][6].y + bv1.z;
        o1.w = acc[mi][7].x + acc[mi][7].y + bv1.w;
        float* cp = &C[(m0 + mp * 4 + mi) * N + nb];
        *(float4*)cp = o0;
        *(float4*)(cp + 4) = o1;
    }
}

// ---------------------------------------------------------------------------
// Small GEMM (epilogue, ~31us): 32x32 tile, N = gridDim.x*32.
// ---------------------------------------------------------------------------
__global__ __launch_bounds__(256) void gemm_nt_small(
    const float* __restrict__ A, const float* __restrict__ B,
    const float* __restrict__ bias, float* __restrict__ C, int K)
{
    __shared__ __align__(16) float2 As[32 * 34];
    __shared__ __align__(16) float2 Bs[32 * 34];

    const int tid = threadIdx.x;
    const int m0 = blockIdx.y * 32, n0 = blockIdx.x * 32;
    const int mp = tid >> 4, np = tid & 15;
    const int lm1 = tid >> 4, lk1 = tid & 15;
    const int lm2 = (tid + 256) >> 4, lk2 = tid & 15;

    float2 a00 = {0.f, 0.f}, a01 = {0.f, 0.f}, a10 = {0.f, 0.f}, a11 = {0.f, 0.f};

    for (int kc = 0; kc < K; kc += 64) {
        float4 va1 = *(const float4*)&A[(m0 + lm1) * K + kc + 4 * lk1];
        float4 va2 = *(const float4*)&A[(m0 + lm2) * K + kc + 4 * lk2];
        float4 vb1 = *(const float4*)&B[(n0 + lm1) * K + kc + 4 * lk1];
        float4 vb2 = *(const float4*)&B[(n0 + lm2) * K + kc + 4 * lk2];
        __syncthreads();
        As[(2 * lk1) * 34 + lm1]     = make_float2(va1.x, va1.y);
        As[(2 * lk1 + 1) * 34 + lm1] = make_float2(va1.z, va1.w);
        As[(2 * lk2) * 34 + lm2]     = make_float2(va2.x, va2.y);
        As[(2 * lk2 + 1) * 34 + lm2] = make_float2(va2.z, va2.w);
        Bs[(2 * lk1) * 34 + lm1]     = make_float2(vb1.x, vb1.y);
        Bs[(2 * lk1 + 1) * 34 + lm1] = make_float2(vb1.z, vb1.w);
        Bs[(2 * lk2) * 34 + lm2]     = make_float2(vb2.x, vb2.y);
        Bs[(2 * lk2 + 1) * 34 + lm2] = make_float2(vb2.z, vb2.w);
        __syncthreads();
        #pragma unroll
        for (int k2 = 0; k2 < 32; ++k2) {
            float4 xa = *(const float4*)&As[k2 * 34 + 2 * mp];
            float4 wb = *(const float4*)&Bs[k2 * 34 + 2 * np];
            float2 xl = {xa.x, xa.y}, xh = {xa.z, xa.w};
            float2 wl = {wb.x, wb.y}, wh = {wb.z, wb.w};
            a00 = ffma2(xl, wl, a00);
            a01 = ffma2(xl, wh, a01);
            a10 = ffma2(xh, wl, a10);
            a11 = ffma2(xh, wh, a11);
        }
    }

    const int N = gridDim.x * 32;
    const int m = m0 + 2 * mp, n = n0 + 2 * np;
    const float b0v = bias[n], b1v = bias[n + 1];
    C[m * N + n]           = a00.x + a00.y + b0v;
    C[m * N + n + 1]       = a01.x + a01.y + b1v;
    C[(m + 1) * N + n]     = a10.x + a10.y + b0v;
    C[(m + 1) * N + n + 1] = a11.x + a11.y + b1v;
}

// ---------------------------------------------------------------------------
// Init: zero state + barrier vars (every replay for determinism)
// ---------------------------------------------------------------------------
__global__ void init_kernel()
{
    int i = blockIdx.x * blockDim.x + threadIdx.x;
    int nth = gridDim.x * blockDim.x;
    for (int j = i; j < BATCH * HID; j += nth) g_s[0][j] = 0.0f;
    if (i < RGROUPS) { g_cnt[i] = 0; g_phase[i] = 0; }
}

// ---------------------------------------------------------------------------
// Persistent recurrence kernel.
// 128 CTAs (4 groups x 32 slices), 256 threads, 1 CTA/SM.
// Thread tile 4b x 4h f32x2, 8-way K-split (one k-group kg per warp).
// Smem layouts exploit broadcast dedup:
//   Wws[kg][i][h]: i = k2 within group (64), h padded 32->34 float2
//   Ss [kg][i][b]: b padded 16->18 float2
// Partials P[8][514] aliased over Ss (syncs guard the alias).
// ---------------------------------------------------------------------------
#define WW_F2    (8 * 64 * 34)                 // 17408 float2 = 139264 B
#define SS_OFF   (WW_F2 * 8)                   // bytes
#define RNN_SMEM (SS_OFF + 8 * 64 * 18 * 8)    // + 73728 = 212992 B

__global__ __launch_bounds__(256, 1) void rnn_step_kernel(
    const float* __restrict__ Ww, const float* __restrict__ bw)
{
    extern __shared__ __align__(16) char smem[];
    float2* Wws = (float2*)smem;
    float2* Ss  = (float2*)(smem + SS_OFF);
    float*  P   = (float*)(smem + SS_OFF);     // alias (guarded by syncs)

    const int tid   = threadIdx.x;
    const int g     = blockIdx.x >> 5;
    const int slice = blockIdx.x & 31;
    const int h0    = slice * RHS;
    const int b0    = g * RBPG;

    // One-time: load Ww slice [32h x 1024k] into [kg][i][h] layout
    for (int idx = tid; idx < RHS * 256; idx += 256) {
        int h = idx >> 8, j = idx & 255;          // j: float4 index over k
        float4 v = *(const float4*)&Ww[(h0 + h) * HID + 4 * j];
        int kg = j >> 5;            // k2 = 2j; kg = k2 >> 6
        int i  = 2 * (j & 31);      // i = k2 & 63
        Wws[(kg * 64 + i) * 34 + h]     = make_float2(v.x, v.y);
        Wws[(kg * 64 + i + 1) * 34 + h] = make_float2(v.z, v.w);
    }

    // compute-thread coords: warp = kg, within warp hg(8) x bg(4)
    const int kg = tid >> 5, hg = (tid >> 2) & 7, bg = tid & 3;
    const float2* sBase = Ss  + (kg * 64) * 18 + bg * 4;
    const float2* wBase = Wws + (kg * 64) * 34 + hg * 4;

    // staging coords
    const int st_b = (tid >> 4) & 15;
    const int st_j = tid & 15;

    // finalize coords: thread handles outputs o = 2*tid, 2*tid+1
    const int fb = tid >> 4;            // local batch 0..15
    const int fh = (tid & 15) * 2;      // h within slice, even
    const float2 bwv = *(const float2*)&bw[h0 + fh];
    const float* xup = &g_xu[(size_t)(b0 + fb) * SEQ * HID + h0 + fh];

    for (int t = 0; t < SEQ; ++t) {
        const int cur = t & 1, nxt = cur ^ 1;
        const float2 xv = *(const float2*)(xup + (size_t)t * HID);  // prefetch

        // stage s[16b][1024k] -> Ss[kg][i][b]
        {
            const float* sc = &g_s[cur][(b0 + st_b) * HID];
            #pragma unroll
            for (int v = 0; v < 16; ++v) {
                int j = v * 16 + st_j;
                float4 sv4 = *(const float4*)&sc[4 * j];
                int skg = j >> 5;
                int si  = 2 * (j & 31);
                float2* dst = Ss + (skg * 64 + si) * 18 + st_b;
                dst[0]  = make_float2(sv4.x, sv4.y);
                dst[18] = make_float2(sv4.z, sv4.w);
            }
        }
        __syncthreads();

        // compute 4b x 4h over this kg's 64 k2
        float2 acc[4][4];
        #pragma unroll
        for (int c = 0; c < 4; ++c)
            #pragma unroll
            for (int hh = 0; hh < 4; ++hh) acc[c][hh] = make_float2(0.f, 0.f);

        #pragma unroll 4
        for (int i = 0; i < 64; ++i) {
            float4 s4a = *(const float4*)(sBase + i * 18);
            float4 s4b = *(const float4*)(sBase + i * 18 + 2);
            float4 w4a = *(const float4*)(wBase + i * 34);
            float4 w4b = *(const float4*)(wBase + i * 34 + 2);
            float2 sv[4] = { {s4a.x, s4a.y}, {s4a.z, s4a.w},
                             {s4b.x, s4b.y}, {s4b.z, s4b.w} };
            float2 wv[4] = { {w4a.x, w4a.y}, {w4a.z, w4a.w},
                             {w4b.x, w4b.y}, {w4b.z, w4b.w} };
            #pragma unroll
            for (int c = 0; c < 4; ++c)
                #pragma unroll
                for (int hh = 0; hh < 4; ++hh)
                    acc[c][hh] = ffma2(sv[c], wv[hh], acc[c][hh]);
        }
        __syncthreads();   // all Ss reads done before alias write

        // write partials: P[kg][o], o = (bg*4+c)*32 + hg*4 + hh
        #pragma unroll
        for (int c = 0; c < 4; ++c) {
            int o = (bg * 4 + c) * 32 + hg * 4;
            *(float2*)&P[kg * 514 + o] =
                make_float2(acc[c][0].x + acc[c][0].y, acc[c][1].x + acc[c][1].y);
            *(float2*)&P[kg * 514 + o + 2] =
                make_float2(acc[c][2].x + acc[c][2].y, acc[c][3].x + acc[c][3].y);
        }
        __syncthreads();

        // reduce over 8 kg + xu + bias, tanh, write next state
        float2 y = make_float2(0.f, 0.f);
        #pragma unroll
        for (int k = 0; k < 8; ++k) {
            float2 p = *(const float2*)&P[k * 514 + 2 * tid];
            y.x += p.x; y.y += p.y;
        }
        y.x += xv.x + bwv.x;
        y.y += xv.y + bwv.y;
        float2 sn = make_float2(accurate_tanh(y.x), accurate_tanh(y.y));
        *(float2*)&g_s[nxt][(b0 + fb) * HID + h0 + fh] = sn;

        // group barrier (32 slice-CTAs of this batch-group)
        if (t < SEQ - 1) {
            __threadfence();
            __syncthreads();
            if (tid == 0) {
                unsigned a = atomicAdd(&g_cnt[g], 1);
                if (a == RSLICES - 1) {
                    atomicExch(&g_cnt[g], 0);
                    __threadfence();
                    atomicExch(&g_phase[g], (unsigned)(t + 1));
                } else {
                    while (*(volatile unsigned*)&g_phase[g] < (unsigned)(t + 1)) { }
                }
                __threadfence();
            }
            __syncthreads();
        }
    }
}

// ---------------------------------------------------------------------------
// kernel_launch
// ---------------------------------------------------------------------------
extern "C" void kernel_launch(void* const* d_in, const int* in_sizes, int n_in,
                              void* d_out, int out_size)
{
    const float* x  = (const float*)d_in[0];
    const float* Wu = (const float*)d_in[1];
    const float* bu = (const float*)d_in[2];
    const float* Ww = (const float*)d_in[3];
    const float* bw = (const float*)d_in[4];
    const float* Wv = (const float*)d_in[5];
    const float* bv = (const float*)d_in[6];
    float* out = (float*)d_out;
    (void)in_sizes; (void)n_in; (void)out_size;

    static bool attr_set = false;
    if (!attr_set) {
        cudaFuncSetAttribute(rnn_step_kernel,
                             cudaFuncAttributeMaxDynamicSharedMemorySize, RNN_SMEM);
        attr_set = true;
    }

    void* xu_ptr = nullptr;
    void* s_ptr  = nullptr;
    cudaGetSymbolAddress(&xu_ptr, g_xu);
    cudaGetSymbolAddress(&s_ptr, g_s);   // buffer 0 == final state (SEQ even)

    // 0) reset state + barriers (every replay)
    init_kernel<<<64, 256>>>();

    // 1) xu = x @ Wu^T + bu   (M=32768, N=1024, K=512)
    gemm_nt_big<<<dim3(HID / 128, (BATCH * SEQ) / 64), 256>>>(
        x, Wu, bu, (float*)xu_ptr, INDIM, HID);

    // 2) recurrence (persistent, 128 co-resident CTAs)
    rnn_step_kernel<<<RGROUPS * RSLICES, 256, RNN_SMEM>>>(Ww, bw);

    // 3) out = s_final @ Wv^T + bv   (M=64, N=512, K=1024)
    gemm_nt_small<<<dim3(OUTDIM / 32, BATCH / 32), 256>>>(
        (const float*)s_ptr, Wv, bv, out, HID);
}